// round 13
// baseline (speedup 1.0000x reference)
#include <cuda_runtime.h>
#include <cuda_fp16.h>
#include <cstdint>

#define Nn     100000
#define ROWS1  600000

// ---------------- device scratch (static globals: allocation-free) ----------
__device__ __align__(1024) __half g_W1img[2][2][4][8192];  // [y][comp][chunk][128n x 64k] swizzled
__device__ __align__(1024) __half g_W2img[2][4][8192];     // [comp][chunk][...]
__device__ __align__(128)  float  g_outs[(size_t)ROWS1 * 128];
__device__ __align__(128)  float  g_means[(size_t)ROWS1 * 128];

// ---------------- helpers ---------------------------------------------------
static __device__ __forceinline__ uint32_t smem_u32(const void* p) {
    uint32_t a;
    asm("{ .reg .u64 t; cvta.to.shared.u64 t, %1; cvt.u32.u64 %0, t; }" : "=r"(a) : "l"(p));
    return a;
}
static __device__ __forceinline__ void ldm4(uint32_t* r, uint32_t addr) {
    asm volatile("ldmatrix.sync.aligned.m8n8.x4.shared.b16 {%0,%1,%2,%3}, [%4];"
                 : "=r"(r[0]), "=r"(r[1]), "=r"(r[2]), "=r"(r[3]) : "r"(addr));
}
static __device__ __forceinline__ void mma16816(float* c, const uint32_t* a,
                                                uint32_t b0, uint32_t b1) {
    asm volatile("mma.sync.aligned.m16n8k16.row.col.f32.f16.f16.f32 "
                 "{%0,%1,%2,%3}, {%4,%5,%6,%7}, {%8,%9}, {%0,%1,%2,%3};"
                 : "+f"(c[0]), "+f"(c[1]), "+f"(c[2]), "+f"(c[3])
                 : "r"(a[0]), "r"(a[1]), "r"(a[2]), "r"(a[3]), "r"(b0), "r"(b1));
}
// f16-accumulate variant: D/C are 2 packed f16x2 regs
static __device__ __forceinline__ void mma16816h(uint32_t* c, const uint32_t* a,
                                                 uint32_t b0, uint32_t b1) {
    asm volatile("mma.sync.aligned.m16n8k16.row.col.f16.f16.f16.f16 "
                 "{%0,%1}, {%2,%3,%4,%5}, {%6,%7}, {%0,%1};"
                 : "+r"(c[0]), "+r"(c[1])
                 : "r"(a[0]), "r"(a[1]), "r"(a[2]), "r"(a[3]), "r"(b0), "r"(b1));
}
static __device__ __forceinline__ void barsync(int id, int cnt) {
    asm volatile("bar.sync %0, %1;" :: "r"(id), "r"(cnt) : "memory");
}
static __device__ __forceinline__ void bararrive(int id, int cnt) {
    asm volatile("bar.arrive %0, %1;" :: "r"(id), "r"(cnt) : "memory");
}
// swizzled byte offset inside a [128row][64k fp16] tile (128B rows, 16B units)
static __device__ __forceinline__ int swz(int row, int unit16) {
    int off = row * 128 + unit16 * 16;
    return off ^ ((off >> 3) & 0x70);
}

// ============================================================================
// prep: split weights fp32 -> (hi, lo) fp16, SW128-swizzled SMEM-image layout.
// ============================================================================
__global__ void prep_kernel(const float* __restrict__ Wl1, const float* __restrict__ Wr1,
                            const float* __restrict__ Wlt1, const float* __restrict__ Wrt1,
                            const float* __restrict__ Wl2, const float* __restrict__ Wr2,
                            const float* __restrict__ Wlt2, const float* __restrict__ Wrt2)
{
    int uid = blockIdx.x * blockDim.x + threadIdx.x;
    if (uid >= 8192 + 4096) return;

    const float *WL, *WR;
    char *hibase, *lobase;
    int v, u, chunk, n, k8;
    if (uid < 8192) {                       // layer 1
        v = uid;
        int y = v >> 12; v &= 4095;
        chunk = v >> 10; v &= 1023;
        n = v >> 3;  k8 = v & 7;
        u = y * 64 + (n >> 1);
        bool zsel = n & 1;
        WL = zsel ? Wl1 : Wlt1;
        WR = zsel ? Wr1 : Wrt1;
        hibase = (char*)&g_W1img[y][0][chunk][0];
        lobase = (char*)&g_W1img[y][1][chunk][0];
    } else {                                // layer 2
        v = uid - 8192;
        chunk = v >> 10; v &= 1023;
        n = v >> 3;  k8 = v & 7;
        u = n >> 1;
        bool zsel = n & 1;
        WL = zsel ? Wl2 : Wlt2;
        WR = zsel ? Wr2 : Wrt2;
        hibase = (char*)&g_W2img[0][chunk][0];
        lobase = (char*)&g_W2img[1][chunk][0];
    }
    int off = n * 128 + k8 * 16;
    off ^= (off >> 3) & 0x70;
    uint32_t hu[4], lu[4];
    #pragma unroll
    for (int j = 0; j < 4; j++) {
        float f0, f1;
        int kg = chunk * 64 + k8 * 8 + 2 * j;
        f0 = (kg < 128) ? WL[u * 128 + kg] : WR[u * 128 + kg - 128];
        kg++;
        f1 = (kg < 128) ? WL[u * 128 + kg] : WR[u * 128 + kg - 128];
        __half h0 = __float2half_rn(f0), h1 = __float2half_rn(f1);
        __half l0 = __float2half_rn(f0 - __half2float(h0));
        __half l1 = __float2half_rn(f1 - __half2float(h1));
        __half2 hp = __halves2half2(h0, h1), lp = __halves2half2(l0, l1);
        hu[j] = *(uint32_t*)&hp; lu[j] = *(uint32_t*)&lp;
    }
    *(uint4*)(hibase + off) = make_uint4(hu[0], hu[1], hu[2], hu[3]);
    *(uint4*)(lobase + off) = make_uint4(lu[0], lu[1], lu[2], lu[3]);
}

// ============================================================================
// mean1: g_means[r] = (r<Nn) ? mean of 5 h1 rows : mean of 2 h2 rows
// ============================================================================
__global__ void mean1_kernel(const float* __restrict__ h1, const float* __restrict__ h2)
{
    int idx = blockIdx.x * blockDim.x + threadIdx.x;
    if (idx >= ROWS1 * 32) return;
    int r = idx >> 5, j = idx & 31;
    float4 s;
    if (r < Nn) {
        const float4* p = (const float4*)(h1 + (size_t)r * 640) + j;
        float4 a = p[0], b = p[32], c = p[64], d = p[96], e = p[128];
        s.x = (a.x + b.x + c.x + d.x + e.x) * 0.2f;
        s.y = (a.y + b.y + c.y + d.y + e.y) * 0.2f;
        s.z = (a.z + b.z + c.z + d.z + e.z) * 0.2f;
        s.w = (a.w + b.w + c.w + d.w + e.w) * 0.2f;
    } else {
        const float4* p = (const float4*)(h2 + (size_t)(r - Nn) * 256) + j;
        float4 a = p[0], b = p[32];
        s.x = (a.x + b.x) * 0.5f;
        s.y = (a.y + b.y) * 0.5f;
        s.z = (a.z + b.z) * 0.5f;
        s.w = (a.w + b.w) * 0.5f;
    }
    *((float4*)(g_means + (size_t)r * 128) + j) = s;
}

// mean for layer 2: g_means[r] = mean of 5 g_outs rows (h1p block)
__global__ void mean2_kernel()
{
    int idx = blockIdx.x * blockDim.x + threadIdx.x;
    if (idx >= Nn * 32) return;
    int r = idx >> 5, j = idx & 31;
    const float4* p = (const float4*)(g_outs + ((size_t)Nn + (size_t)r * 5) * 128) + j;
    float4 a = p[0], b = p[32], c = p[64], d = p[96], e = p[128];
    float4 s;
    s.x = (a.x + b.x + c.x + d.x + e.x) * 0.2f;
    s.y = (a.y + b.y + c.y + d.y + e.y) * 0.2f;
    s.z = (a.z + b.z + c.z + d.z + e.z) * 0.2f;
    s.w = (a.w + b.w + c.w + d.w + e.w) * 0.2f;
    *((float4*)(g_means + (size_t)r * 128) + j) = s;
}

// ============================================================================
// PERSISTENT warp-specialized GEMM, fp16x3 split on mma.sync (HMMA).
// Pass 1 (Ah*Bh) -> f32 accum; passes 2,3 (Ah*Bl, Al*Bh) -> shared f16 accum.
// 384 threads: warps 0-7 MMA consumers (2M x 4N), warps 8-11 producers.
// B resident (128 KB). A TRIPLE-buffered (3 x 32 KB): producers run up to
// ~2.5 chunks ahead (eager LDG before stage wait), so consumers never stall
// on BAR_READY. Named-barrier handoff.
// ============================================================================
#define SM_B    1024
#define SM_A    132096
#define SM_TOT  230400            /* 1024 + 131072 + 3*32768 */
#define NTHR    384
#define NSTAGE  3
#define BAR_READY(s)    (1 + (s))
#define BAR_CONS(s)     (4 + (s))

extern "C" __global__ void __launch_bounds__(NTHR, 1)
signn_tile_kernel(int mode,
                  const float* __restrict__ h0,
                  const float* __restrict__ h1,
                  float* __restrict__ outp)
{
    extern __shared__ __align__(1024) char smem[];
    const uint32_t sb = smem_u32(smem);
    const int tid = threadIdx.x, lane = tid & 31;
    const int y = blockIdx.x;
    const int nrows = mode ? Nn : ROWS1;
    const int ntiles = (nrows + 127) >> 7;
    const int stride = gridDim.y;

    // ---- stage B once (resident, 128 KB), all 384 threads ----
    {
        const uint4* bsrc = mode ? (const uint4*)&g_W2img[0][0][0]
                                 : (const uint4*)&g_W1img[y][0][0][0];
        uint4* bdst = (uint4*)(smem + SM_B);
        for (int i = tid; i < 8192; i += NTHR) bdst[i] = bsrc[i];
    }
    __syncthreads();

    if (tid < 256) {
        // ===================== CONSUMER: 8 MMA warps =====================
        const int wid = tid >> 5;
        const int wm = wid & 1;          // M warp group: 64 rows
        const int wn = wid >> 1;         // N warp group: 32 cols
        const int lrow = (lane & 7) + ((lane >> 3) & 1) * 8;
        const int lcol = lane >> 4;
        const int qlane = lane >> 2, tlane = lane & 3;

        int s = 0;
        for (int t = blockIdx.y; t < ntiles; t += stride) {
            const int row0 = t * 128;
            float acc[64];
            uint32_t accl[32];               // f16x2 accum for low passes
            #pragma unroll
            for (int i = 0; i < 64; i++) acc[i] = 0.0f;
            #pragma unroll
            for (int i = 0; i < 32; i++) accl[i] = 0u;

            #pragma unroll
            for (int c = 0; c < 4; c++) {
                barsync(BAR_READY(s), NTHR);          // wait A stage s filled
                const uint32_t aBase = sb + SM_A + s * 32768;
                const uint32_t bBase = sb + SM_B + c * 16384;
                #pragma unroll
                for (int kk = 0; kk < 4; kk++) {
                    uint32_t AH[4][4], AL[4][4], BH[2][4], BL[2][4];
                    #pragma unroll
                    for (int mf = 0; mf < 4; mf++) {
                        int r = wm * 64 + mf * 16 + lrow;
                        int u = kk * 2 + lcol;
                        ldm4(AH[mf], aBase + swz(r, u));
                        ldm4(AL[mf], aBase + 16384 + swz(r, u));
                    }
                    #pragma unroll
                    for (int nb = 0; nb < 2; nb++) {
                        int r = wn * 32 + nb * 16 + lrow;
                        int u = kk * 2 + lcol;
                        ldm4(BH[nb], bBase + swz(r, u));
                    }
                    // pass 1 (f32 acc) + pass 3 (f16 acc) use BH
                    #pragma unroll
                    for (int mf = 0; mf < 4; mf++)
                        #pragma unroll
                        for (int nb = 0; nb < 2; nb++)
                            #pragma unroll
                            for (int h = 0; h < 2; h++) {
                                mma16816(acc + mf * 16 + (nb * 2 + h) * 4,
                                         AH[mf], BH[nb][h], BH[nb][2 + h]);
                                mma16816h(accl + mf * 8 + (nb * 2 + h) * 2,
                                          AL[mf], BH[nb][h], BH[nb][2 + h]);
                            }
                    // pass 2 (f16 acc) uses BL
                    #pragma unroll
                    for (int nb = 0; nb < 2; nb++) {
                        int r = wn * 32 + nb * 16 + lrow;
                        int u = kk * 2 + lcol;
                        ldm4(BL[nb], bBase + 65536 + swz(r, u));
                    }
                    #pragma unroll
                    for (int mf = 0; mf < 4; mf++)
                        #pragma unroll
                        for (int nb = 0; nb < 2; nb++)
                            #pragma unroll
                            for (int h = 0; h < 2; h++)
                                mma16816h(accl + mf * 8 + (nb * 2 + h) * 2,
                                          AH[mf], BL[nb][h], BL[nb][2 + h]);
                }
                bararrive(BAR_CONS(s), NTHR);         // A stage s free
                s = (s == NSTAGE - 1) ? 0 : s + 1;
            }

            // epilogue: merge f32 + f16 accums, apply sigmoid*spike
            #pragma unroll
            for (int mf = 0; mf < 4; mf++) {
                int r0 = row0 + wm * 64 + mf * 16 + qlane;
                #pragma unroll
                for (int nn = 0; nn < 4; nn++) {
                    const float* cc = acc + mf * 16 + nn * 4;
                    const uint32_t* cl = accl + mf * 8 + nn * 2;
                    int u = wn * 16 + nn * 4 + tlane;
                    #pragma unroll
                    for (int rr = 0; rr < 2; rr++) {
                        int r = r0 + rr * 8;
                        if (r < nrows) {
                            float2 lo = __half22float2(*(const __half2*)&cl[rr]);
                            float tt = cc[rr * 2 + 0] + lo.x;
                            float zz = cc[rr * 2 + 1] + lo.y;
                            float o = (tt >= 1.0f) ? (1.0f / (1.0f + __expf(-zz))) : 0.0f;
                            if (mode) outp[(size_t)r * 64 + u] = o;
                            else      g_outs[(size_t)r * 128 + y * 64 + u] = o;
                        }
                    }
                }
            }
        }
    } else {
        // ===================== PRODUCER: 4 warps (128 threads) ============
        const int ptid = tid - 256;
        const int k8 = ptid & 7;
        int s = 0;
        long jcount = 0;
        for (int t = blockIdx.y; t < ntiles; t += stride) {
            const int row0 = t * 128;
            #pragma unroll
            for (int c = 0; c < 4; c++) {
                // eager fetch: LDG for this chunk issued BEFORE the stage wait
                float4 pre[16];
                #pragma unroll
                for (int q = 0; q < 8; q++) {
                    int m = (ptid >> 3) + q * 16;
                    int r = row0 + m;
                    if (r < nrows) {
                        const float* p;
                        if (c < 2) {
                            const float* selfp = mode
                                ? g_outs + (size_t)r * 128
                                : ((r < Nn) ? h0 + (size_t)r * 128
                                            : h1 + (size_t)(r - Nn) * 128);
                            p = selfp + c * 64 + k8 * 8;
                        } else {
                            p = g_means + (size_t)r * 128 + (c - 2) * 64 + k8 * 8;
                        }
                        pre[2 * q]     = *(const float4*)p;
                        pre[2 * q + 1] = *(const float4*)(p + 4);
                    } else {
                        pre[2 * q] = pre[2 * q + 1] = make_float4(0.f, 0.f, 0.f, 0.f);
                    }
                }

                if (jcount >= NSTAGE) barsync(BAR_CONS(s), NTHR);

                char* Ah = smem + SM_A + s * 32768;
                char* Al = Ah + 16384;
                #pragma unroll
                for (int q = 0; q < 8; q++) {
                    int m = (ptid >> 3) + q * 16;
                    float f[8];
                    f[0]=pre[2*q].x; f[1]=pre[2*q].y; f[2]=pre[2*q].z; f[3]=pre[2*q].w;
                    f[4]=pre[2*q+1].x; f[5]=pre[2*q+1].y; f[6]=pre[2*q+1].z; f[7]=pre[2*q+1].w;
                    uint32_t hu[4], lu[4];
                    #pragma unroll
                    for (int j = 0; j < 4; j++) {
                        float x0 = f[2*j], x1 = f[2*j+1];
                        __half hh0 = __float2half_rn(x0), hh1 = __float2half_rn(x1);
                        __half ll0 = __float2half_rn(x0 - __half2float(hh0));
                        __half ll1 = __float2half_rn(x1 - __half2float(hh1));
                        __half2 hp = __halves2half2(hh0, hh1), lp = __halves2half2(ll0, ll1);
                        hu[j] = *(uint32_t*)&hp; lu[j] = *(uint32_t*)&lp;
                    }
                    int off = swz(m, k8);
                    *(uint4*)(Ah + off) = make_uint4(hu[0], hu[1], hu[2], hu[3]);
                    *(uint4*)(Al + off) = make_uint4(lu[0], lu[1], lu[2], lu[3]);
                }
                asm volatile("membar.cta;" ::: "memory");
                bararrive(BAR_READY(s), NTHR);
                s = (s == NSTAGE - 1) ? 0 : s + 1;
                jcount++;
            }
        }
    }
}

// ============================================================================
extern "C" void kernel_launch(void* const* d_in, const int* in_sizes, int n_in,
                              void* d_out, int out_size)
{
    const float* h0   = (const float*)d_in[0];
    const float* h1   = (const float*)d_in[1];
    const float* h2   = (const float*)d_in[2];
    const float* Wl1  = (const float*)d_in[3];
    const float* Wr1  = (const float*)d_in[4];
    const float* Wlt1 = (const float*)d_in[5];
    const float* Wrt1 = (const float*)d_in[6];
    const float* Wl2  = (const float*)d_in[7];
    const float* Wr2  = (const float*)d_in[8];
    const float* Wlt2 = (const float*)d_in[9];
    const float* Wrt2 = (const float*)d_in[10];
    float* out = (float*)d_out;

    cudaFuncSetAttribute(signn_tile_kernel,
                         cudaFuncAttributeMaxDynamicSharedMemorySize, SM_TOT);

    prep_kernel<<<48, 256>>>(Wl1, Wr1, Wlt1, Wrt1, Wl2, Wr2, Wlt2, Wrt2);
    mean1_kernel<<<(ROWS1 * 32 + 255) / 256, 256>>>(h1, h2);

    dim3 g1(2, 74);                    // 148 persistent CTAs
    signn_tile_kernel<<<g1, NTHR, SM_TOT>>>(0, h0, h1, nullptr);

    mean2_kernel<<<(Nn * 32 + 255) / 256, 256>>>();

    dim3 g2(1, 148);                   // 148 persistent CTAs
    signn_tile_kernel<<<g2, NTHR, SM_TOT>>>(1, nullptr, nullptr, out);
}

// round 14
// speedup vs baseline: 1.0749x; 1.0749x over previous
#include <cuda_runtime.h>
#include <cuda_fp16.h>
#include <cstdint>

#define Nn     100000
#define ROWS1  600000

// ---------------- device scratch (static globals: allocation-free) ----------
__device__ __align__(1024) __half g_W1img[2][2][4][8192];  // [y][comp][chunk][128n x 64k] swizzled
__device__ __align__(1024) __half g_W2img[2][4][8192];     // [comp][chunk][...]
__device__ __align__(128)  float  g_outs[(size_t)ROWS1 * 128];
__device__ __align__(128)  float  g_means[(size_t)Nn * 128];   // 5-row means only (r < Nn)

// ---------------- helpers ---------------------------------------------------
static __device__ __forceinline__ uint32_t smem_u32(const void* p) {
    uint32_t a;
    asm("{ .reg .u64 t; cvta.to.shared.u64 t, %1; cvt.u32.u64 %0, t; }" : "=r"(a) : "l"(p));
    return a;
}
static __device__ __forceinline__ void ldm4(uint32_t* r, uint32_t addr) {
    asm volatile("ldmatrix.sync.aligned.m8n8.x4.shared.b16 {%0,%1,%2,%3}, [%4];"
                 : "=r"(r[0]), "=r"(r[1]), "=r"(r[2]), "=r"(r[3]) : "r"(addr));
}
static __device__ __forceinline__ void mma16816(float* c, const uint32_t* a,
                                                uint32_t b0, uint32_t b1) {
    asm volatile("mma.sync.aligned.m16n8k16.row.col.f32.f16.f16.f32 "
                 "{%0,%1,%2,%3}, {%4,%5,%6,%7}, {%8,%9}, {%0,%1,%2,%3};"
                 : "+f"(c[0]), "+f"(c[1]), "+f"(c[2]), "+f"(c[3])
                 : "r"(a[0]), "r"(a[1]), "r"(a[2]), "r"(a[3]), "r"(b0), "r"(b1));
}
// f16-accumulate variant: D/C are 2 packed f16x2 regs
static __device__ __forceinline__ void mma16816h(uint32_t* c, const uint32_t* a,
                                                 uint32_t b0, uint32_t b1) {
    asm volatile("mma.sync.aligned.m16n8k16.row.col.f16.f16.f16.f16 "
                 "{%0,%1}, {%2,%3,%4,%5}, {%6,%7}, {%0,%1};"
                 : "+r"(c[0]), "+r"(c[1])
                 : "r"(a[0]), "r"(a[1]), "r"(a[2]), "r"(a[3]), "r"(b0), "r"(b1));
}
static __device__ __forceinline__ void barsync(int id, int cnt) {
    asm volatile("bar.sync %0, %1;" :: "r"(id), "r"(cnt) : "memory");
}
static __device__ __forceinline__ void bararrive(int id, int cnt) {
    asm volatile("bar.arrive %0, %1;" :: "r"(id), "r"(cnt) : "memory");
}
// swizzled byte offset inside a [128row][64k fp16] tile (128B rows, 16B units)
static __device__ __forceinline__ int swz(int row, int unit16) {
    int off = row * 128 + unit16 * 16;
    return off ^ ((off >> 3) & 0x70);
}

// ============================================================================
// prep: split weights fp32 -> (hi, lo) fp16, SW128-swizzled SMEM-image layout.
// ============================================================================
__global__ void prep_kernel(const float* __restrict__ Wl1, const float* __restrict__ Wr1,
                            const float* __restrict__ Wlt1, const float* __restrict__ Wrt1,
                            const float* __restrict__ Wl2, const float* __restrict__ Wr2,
                            const float* __restrict__ Wlt2, const float* __restrict__ Wrt2)
{
    int uid = blockIdx.x * blockDim.x + threadIdx.x;
    if (uid >= 8192 + 4096) return;

    const float *WL, *WR;
    char *hibase, *lobase;
    int v, u, chunk, n, k8;
    if (uid < 8192) {                       // layer 1
        v = uid;
        int y = v >> 12; v &= 4095;
        chunk = v >> 10; v &= 1023;
        n = v >> 3;  k8 = v & 7;
        u = y * 64 + (n >> 1);
        bool zsel = n & 1;
        WL = zsel ? Wl1 : Wlt1;
        WR = zsel ? Wr1 : Wrt1;
        hibase = (char*)&g_W1img[y][0][chunk][0];
        lobase = (char*)&g_W1img[y][1][chunk][0];
    } else {                                // layer 2
        v = uid - 8192;
        chunk = v >> 10; v &= 1023;
        n = v >> 3;  k8 = v & 7;
        u = n >> 1;
        bool zsel = n & 1;
        WL = zsel ? Wl2 : Wlt2;
        WR = zsel ? Wr2 : Wrt2;
        hibase = (char*)&g_W2img[0][chunk][0];
        lobase = (char*)&g_W2img[1][chunk][0];
    }
    int off = n * 128 + k8 * 16;
    off ^= (off >> 3) & 0x70;
    uint32_t hu[4], lu[4];
    #pragma unroll
    for (int j = 0; j < 4; j++) {
        float f0, f1;
        int kg = chunk * 64 + k8 * 8 + 2 * j;
        f0 = (kg < 128) ? WL[u * 128 + kg] : WR[u * 128 + kg - 128];
        kg++;
        f1 = (kg < 128) ? WL[u * 128 + kg] : WR[u * 128 + kg - 128];
        __half h0 = __float2half_rn(f0), h1 = __float2half_rn(f1);
        __half l0 = __float2half_rn(f0 - __half2float(h0));
        __half l1 = __float2half_rn(f1 - __half2float(h1));
        __half2 hp = __halves2half2(h0, h1), lp = __halves2half2(l0, l1);
        hu[j] = *(uint32_t*)&hp; lu[j] = *(uint32_t*)&lp;
    }
    *(uint4*)(hibase + off) = make_uint4(hu[0], hu[1], hu[2], hu[3]);
    *(uint4*)(lobase + off) = make_uint4(lu[0], lu[1], lu[2], lu[3]);
}

// ============================================================================
// mean1 (REDUCED): only r < Nn -> 5-row h1 means. Tail (2-row h2 means) is
// fused into the layer-1 producers.
// ============================================================================
__global__ void mean1_kernel(const float* __restrict__ h1)
{
    int idx = blockIdx.x * blockDim.x + threadIdx.x;
    if (idx >= Nn * 32) return;
    int r = idx >> 5, j = idx & 31;
    const float4* p = (const float4*)(h1 + (size_t)r * 640) + j;
    float4 a = p[0], b = p[32], c = p[64], d = p[96], e = p[128];
    float4 s;
    s.x = (a.x + b.x + c.x + d.x + e.x) * 0.2f;
    s.y = (a.y + b.y + c.y + d.y + e.y) * 0.2f;
    s.z = (a.z + b.z + c.z + d.z + e.z) * 0.2f;
    s.w = (a.w + b.w + c.w + d.w + e.w) * 0.2f;
    *((float4*)(g_means + (size_t)r * 128) + j) = s;
}

// mean for layer 2: g_means[r] = mean of 5 g_outs rows (h1p block), r < Nn
__global__ void mean2_kernel()
{
    int idx = blockIdx.x * blockDim.x + threadIdx.x;
    if (idx >= Nn * 32) return;
    int r = idx >> 5, j = idx & 31;
    const float4* p = (const float4*)(g_outs + ((size_t)Nn + (size_t)r * 5) * 128) + j;
    float4 a = p[0], b = p[32], c = p[64], d = p[96], e = p[128];
    float4 s;
    s.x = (a.x + b.x + c.x + d.x + e.x) * 0.2f;
    s.y = (a.y + b.y + c.y + d.y + e.y) * 0.2f;
    s.z = (a.z + b.z + c.z + d.z + e.z) * 0.2f;
    s.w = (a.w + b.w + c.w + d.w + e.w) * 0.2f;
    *((float4*)(g_means + (size_t)r * 128) + j) = s;
}

// ============================================================================
// PERSISTENT warp-specialized GEMM, fp16x3 split on mma.sync (HMMA).
// Pass 1 (Ah*Bh) -> f32 accum; passes 2,3 (Ah*Bl, Al*Bh) -> shared f16 accum.
// 384 threads: warps 0-7 MMA consumers (2M x 4N), warps 8-11 producers.
// Producer c>=2: r<Nn -> read g_means (precomputed 5-row means);
//                r>=Nn (layer-1 tail) -> FUSED 2-row h2 mean (4 loads/unit).
// B resident (128 KB). A double-buffered (2 x 32 KB). Named-barrier handoff.
// ============================================================================
#define SM_B    1024
#define SM_A    132096
#define SM_TOT  197632
#define NTHR    384
#define BAR_READY(s)    (1 + (s))
#define BAR_CONS(s)     (3 + (s))

extern "C" __global__ void __launch_bounds__(NTHR, 1)
signn_tile_kernel(int mode,
                  const float* __restrict__ h0,
                  const float* __restrict__ h1,
                  const float* __restrict__ h2,
                  float* __restrict__ outp)
{
    extern __shared__ __align__(1024) char smem[];
    const uint32_t sb = smem_u32(smem);
    const int tid = threadIdx.x, lane = tid & 31;
    const int y = blockIdx.x;
    const int nrows = mode ? Nn : ROWS1;
    const int ntiles = (nrows + 127) >> 7;
    const int stride = gridDim.y;

    // ---- stage B once (resident, 128 KB), all 384 threads ----
    {
        const uint4* bsrc = mode ? (const uint4*)&g_W2img[0][0][0]
                                 : (const uint4*)&g_W1img[y][0][0][0];
        uint4* bdst = (uint4*)(smem + SM_B);
        for (int i = tid; i < 8192; i += NTHR) bdst[i] = bsrc[i];
    }
    __syncthreads();

    if (tid < 256) {
        // ===================== CONSUMER: 8 MMA warps =====================
        const int wid = tid >> 5;
        const int wm = wid & 1;          // M warp group: 64 rows
        const int wn = wid >> 1;         // N warp group: 32 cols
        const int lrow = (lane & 7) + ((lane >> 3) & 1) * 8;
        const int lcol = lane >> 4;
        const int qlane = lane >> 2, tlane = lane & 3;

        int s = 0;
        for (int t = blockIdx.y; t < ntiles; t += stride) {
            const int row0 = t * 128;
            float acc[64];
            uint32_t accl[32];               // f16x2 accum for low passes
            #pragma unroll
            for (int i = 0; i < 64; i++) acc[i] = 0.0f;
            #pragma unroll
            for (int i = 0; i < 32; i++) accl[i] = 0u;

            #pragma unroll
            for (int c = 0; c < 4; c++) {
                barsync(BAR_READY(s), NTHR);          // wait A stage s filled
                const uint32_t aBase = sb + SM_A + s * 32768;
                const uint32_t bBase = sb + SM_B + c * 16384;
                #pragma unroll
                for (int kk = 0; kk < 4; kk++) {
                    uint32_t AH[4][4], AL[4][4], BH[2][4], BL[2][4];
                    #pragma unroll
                    for (int mf = 0; mf < 4; mf++) {
                        int r = wm * 64 + mf * 16 + lrow;
                        int u = kk * 2 + lcol;
                        ldm4(AH[mf], aBase + swz(r, u));
                        ldm4(AL[mf], aBase + 16384 + swz(r, u));
                    }
                    #pragma unroll
                    for (int nb = 0; nb < 2; nb++) {
                        int r = wn * 32 + nb * 16 + lrow;
                        int u = kk * 2 + lcol;
                        ldm4(BH[nb], bBase + swz(r, u));
                    }
                    // pass 1 (f32 acc) + pass 3 (f16 acc) use BH
                    #pragma unroll
                    for (int mf = 0; mf < 4; mf++)
                        #pragma unroll
                        for (int nb = 0; nb < 2; nb++)
                            #pragma unroll
                            for (int h = 0; h < 2; h++) {
                                mma16816(acc + mf * 16 + (nb * 2 + h) * 4,
                                         AH[mf], BH[nb][h], BH[nb][2 + h]);
                                mma16816h(accl + mf * 8 + (nb * 2 + h) * 2,
                                          AL[mf], BH[nb][h], BH[nb][2 + h]);
                            }
                    // pass 2 (f16 acc) uses BL
                    #pragma unroll
                    for (int nb = 0; nb < 2; nb++) {
                        int r = wn * 32 + nb * 16 + lrow;
                        int u = kk * 2 + lcol;
                        ldm4(BL[nb], bBase + 65536 + swz(r, u));
                    }
                    #pragma unroll
                    for (int mf = 0; mf < 4; mf++)
                        #pragma unroll
                        for (int nb = 0; nb < 2; nb++)
                            #pragma unroll
                            for (int h = 0; h < 2; h++)
                                mma16816h(accl + mf * 8 + (nb * 2 + h) * 2,
                                          AH[mf], BL[nb][h], BL[nb][2 + h]);
                }
                bararrive(BAR_CONS(s), NTHR);         // A stage s free
                s ^= 1;
            }

            // epilogue: merge f32 + f16 accums, apply sigmoid*spike
            #pragma unroll
            for (int mf = 0; mf < 4; mf++) {
                int r0 = row0 + wm * 64 + mf * 16 + qlane;
                #pragma unroll
                for (int nn = 0; nn < 4; nn++) {
                    const float* cc = acc + mf * 16 + nn * 4;
                    const uint32_t* cl = accl + mf * 8 + nn * 2;
                    int u = wn * 16 + nn * 4 + tlane;
                    #pragma unroll
                    for (int rr = 0; rr < 2; rr++) {
                        int r = r0 + rr * 8;
                        if (r < nrows) {
                            float2 lo = __half22float2(*(const __half2*)&cl[rr]);
                            float tt = cc[rr * 2 + 0] + lo.x;
                            float zz = cc[rr * 2 + 1] + lo.y;
                            float o = (tt >= 1.0f) ? (1.0f / (1.0f + __expf(-zz))) : 0.0f;
                            if (mode) outp[(size_t)r * 64 + u] = o;
                            else      g_outs[(size_t)r * 128 + y * 64 + u] = o;
                        }
                    }
                }
            }
        }
    } else {
        // ===================== PRODUCER: 4 warps (128 threads) ============
        const int ptid = tid - 256;
        const int k8 = ptid & 7;
        int s = 0;
        long jcount = 0;
        for (int t = blockIdx.y; t < ntiles; t += stride) {
            const int row0 = t * 128;
            #pragma unroll
            for (int c = 0; c < 4; c++) {
                // eager fetch (LDG issued before the stage wait)
                float4 pre[16];
                #pragma unroll
                for (int q = 0; q < 8; q++) {
                    int m = (ptid >> 3) + q * 16;
                    int r = row0 + m;
                    if (r < nrows) {
                        if (c < 2) {
                            const float* selfp = mode
                                ? g_outs + (size_t)r * 128
                                : ((r < Nn) ? h0 + (size_t)r * 128
                                            : h1 + (size_t)(r - Nn) * 128);
                            const float* p = selfp + c * 64 + k8 * 8;
                            pre[2 * q]     = *(const float4*)p;
                            pre[2 * q + 1] = *(const float4*)(p + 4);
                        } else if (mode == 0 && r >= Nn) {
                            // fused 2-row h2 mean (identical arithmetic to old mean1)
                            const float* p = h2 + (size_t)(r - Nn) * 256
                                                + (c - 2) * 64 + k8 * 8;
                            float4 a0 = *(const float4*)p;
                            float4 a1 = *(const float4*)(p + 4);
                            float4 b0 = *(const float4*)(p + 128);
                            float4 b1 = *(const float4*)(p + 132);
                            float4 s0, s1;
                            s0.x = (a0.x + b0.x) * 0.5f; s0.y = (a0.y + b0.y) * 0.5f;
                            s0.z = (a0.z + b0.z) * 0.5f; s0.w = (a0.w + b0.w) * 0.5f;
                            s1.x = (a1.x + b1.x) * 0.5f; s1.y = (a1.y + b1.y) * 0.5f;
                            s1.z = (a1.z + b1.z) * 0.5f; s1.w = (a1.w + b1.w) * 0.5f;
                            pre[2 * q] = s0; pre[2 * q + 1] = s1;
                        } else {
                            const float* p = g_means + (size_t)r * 128
                                                     + (c - 2) * 64 + k8 * 8;
                            pre[2 * q]     = *(const float4*)p;
                            pre[2 * q + 1] = *(const float4*)(p + 4);
                        }
                    } else {
                        pre[2 * q] = pre[2 * q + 1] = make_float4(0.f, 0.f, 0.f, 0.f);
                    }
                }

                if (jcount >= 2) barsync(BAR_CONS(s), NTHR);

                char* Ah = smem + SM_A + s * 32768;
                char* Al = Ah + 16384;
                #pragma unroll
                for (int q = 0; q < 8; q++) {
                    int m = (ptid >> 3) + q * 16;
                    float f[8];
                    f[0]=pre[2*q].x; f[1]=pre[2*q].y; f[2]=pre[2*q].z; f[3]=pre[2*q].w;
                    f[4]=pre[2*q+1].x; f[5]=pre[2*q+1].y; f[6]=pre[2*q+1].z; f[7]=pre[2*q+1].w;
                    uint32_t hu[4], lu[4];
                    #pragma unroll
                    for (int j = 0; j < 4; j++) {
                        float x0 = f[2*j], x1 = f[2*j+1];
                        __half hh0 = __float2half_rn(x0), hh1 = __float2half_rn(x1);
                        __half ll0 = __float2half_rn(x0 - __half2float(hh0));
                        __half ll1 = __float2half_rn(x1 - __half2float(hh1));
                        __half2 hp = __halves2half2(hh0, hh1), lp = __halves2half2(ll0, ll1);
                        hu[j] = *(uint32_t*)&hp; lu[j] = *(uint32_t*)&lp;
                    }
                    int off = swz(m, k8);
                    *(uint4*)(Ah + off) = make_uint4(hu[0], hu[1], hu[2], hu[3]);
                    *(uint4*)(Al + off) = make_uint4(lu[0], lu[1], lu[2], lu[3]);
                }
                asm volatile("membar.cta;" ::: "memory");
                bararrive(BAR_READY(s), NTHR);
                s ^= 1;
                jcount++;
            }
        }
    }
}

// ============================================================================
extern "C" void kernel_launch(void* const* d_in, const int* in_sizes, int n_in,
                              void* d_out, int out_size)
{
    const float* h0   = (const float*)d_in[0];
    const float* h1   = (const float*)d_in[1];
    const float* h2   = (const float*)d_in[2];
    const float* Wl1  = (const float*)d_in[3];
    const float* Wr1  = (const float*)d_in[4];
    const float* Wlt1 = (const float*)d_in[5];
    const float* Wrt1 = (const float*)d_in[6];
    const float* Wl2  = (const float*)d_in[7];
    const float* Wr2  = (const float*)d_in[8];
    const float* Wlt2 = (const float*)d_in[9];
    const float* Wrt2 = (const float*)d_in[10];
    float* out = (float*)d_out;

    cudaFuncSetAttribute(signn_tile_kernel,
                         cudaFuncAttributeMaxDynamicSharedMemorySize, SM_TOT);

    prep_kernel<<<48, 256>>>(Wl1, Wr1, Wlt1, Wrt1, Wl2, Wr2, Wlt2, Wrt2);
    mean1_kernel<<<(Nn * 32 + 255) / 256, 256>>>(h1);    // 5-row part only

    dim3 g1(2, 74);                    // 148 persistent CTAs
    signn_tile_kernel<<<g1, NTHR, SM_TOT>>>(0, h0, h1, h2, nullptr);

    mean2_kernel<<<(Nn * 32 + 255) / 256, 256>>>();

    dim3 g2(1, 148);                   // 148 persistent CTAs
    signn_tile_kernel<<<g2, NTHR, SM_TOT>>>(1, nullptr, nullptr, nullptr, out);
}

// round 15
// speedup vs baseline: 1.0859x; 1.0102x over previous
#include <cuda_runtime.h>
#include <cuda_fp16.h>
#include <cstdint>

#define Nn     100000
#define ROWS1  600000

// ---------------- device scratch (static globals: allocation-free) ----------
__device__ __align__(1024) __half g_W1img[2][2][4][8192];  // [y][comp][chunk][128n x 64k] swizzled
__device__ __align__(1024) __half g_W2img[2][4][8192];     // [comp][chunk][...]
__device__ __align__(128)  float  g_outs[(size_t)ROWS1 * 128];
__device__ __align__(128)  float  g_means[(size_t)Nn * 128];   // layer-1 5-row h1 means only

// ---------------- helpers ---------------------------------------------------
static __device__ __forceinline__ uint32_t smem_u32(const void* p) {
    uint32_t a;
    asm("{ .reg .u64 t; cvta.to.shared.u64 t, %1; cvt.u32.u64 %0, t; }" : "=r"(a) : "l"(p));
    return a;
}
static __device__ __forceinline__ void ldm4(uint32_t* r, uint32_t addr) {
    asm volatile("ldmatrix.sync.aligned.m8n8.x4.shared.b16 {%0,%1,%2,%3}, [%4];"
                 : "=r"(r[0]), "=r"(r[1]), "=r"(r[2]), "=r"(r[3]) : "r"(addr));
}
static __device__ __forceinline__ void mma16816(float* c, const uint32_t* a,
                                                uint32_t b0, uint32_t b1) {
    asm volatile("mma.sync.aligned.m16n8k16.row.col.f32.f16.f16.f32 "
                 "{%0,%1,%2,%3}, {%4,%5,%6,%7}, {%8,%9}, {%0,%1,%2,%3};"
                 : "+f"(c[0]), "+f"(c[1]), "+f"(c[2]), "+f"(c[3])
                 : "r"(a[0]), "r"(a[1]), "r"(a[2]), "r"(a[3]), "r"(b0), "r"(b1));
}
// f16-accumulate variant: D/C are 2 packed f16x2 regs
static __device__ __forceinline__ void mma16816h(uint32_t* c, const uint32_t* a,
                                                 uint32_t b0, uint32_t b1) {
    asm volatile("mma.sync.aligned.m16n8k16.row.col.f16.f16.f16.f16 "
                 "{%0,%1}, {%2,%3,%4,%5}, {%6,%7}, {%0,%1};"
                 : "+r"(c[0]), "+r"(c[1])
                 : "r"(a[0]), "r"(a[1]), "r"(a[2]), "r"(a[3]), "r"(b0), "r"(b1));
}
static __device__ __forceinline__ void barsync(int id, int cnt) {
    asm volatile("bar.sync %0, %1;" :: "r"(id), "r"(cnt) : "memory");
}
static __device__ __forceinline__ void bararrive(int id, int cnt) {
    asm volatile("bar.arrive %0, %1;" :: "r"(id), "r"(cnt) : "memory");
}
// swizzled byte offset inside a [128row][64k fp16] tile (128B rows, 16B units)
static __device__ __forceinline__ int swz(int row, int unit16) {
    int off = row * 128 + unit16 * 16;
    return off ^ ((off >> 3) & 0x70);
}

// ============================================================================
// prep: split weights fp32 -> (hi, lo) fp16, SW128-swizzled SMEM-image layout.
// ============================================================================
__global__ void prep_kernel(const float* __restrict__ Wl1, const float* __restrict__ Wr1,
                            const float* __restrict__ Wlt1, const float* __restrict__ Wrt1,
                            const float* __restrict__ Wl2, const float* __restrict__ Wr2,
                            const float* __restrict__ Wlt2, const float* __restrict__ Wrt2)
{
    int uid = blockIdx.x * blockDim.x + threadIdx.x;
    if (uid >= 8192 + 4096) return;

    const float *WL, *WR;
    char *hibase, *lobase;
    int v, u, chunk, n, k8;
    if (uid < 8192) {                       // layer 1
        v = uid;
        int y = v >> 12; v &= 4095;
        chunk = v >> 10; v &= 1023;
        n = v >> 3;  k8 = v & 7;
        u = y * 64 + (n >> 1);
        bool zsel = n & 1;
        WL = zsel ? Wl1 : Wlt1;
        WR = zsel ? Wr1 : Wrt1;
        hibase = (char*)&g_W1img[y][0][chunk][0];
        lobase = (char*)&g_W1img[y][1][chunk][0];
    } else {                                // layer 2
        v = uid - 8192;
        chunk = v >> 10; v &= 1023;
        n = v >> 3;  k8 = v & 7;
        u = n >> 1;
        bool zsel = n & 1;
        WL = zsel ? Wl2 : Wlt2;
        WR = zsel ? Wr2 : Wrt2;
        hibase = (char*)&g_W2img[0][chunk][0];
        lobase = (char*)&g_W2img[1][chunk][0];
    }
    int off = n * 128 + k8 * 16;
    off ^= (off >> 3) & 0x70;
    uint32_t hu[4], lu[4];
    #pragma unroll
    for (int j = 0; j < 4; j++) {
        float f0, f1;
        int kg = chunk * 64 + k8 * 8 + 2 * j;
        f0 = (kg < 128) ? WL[u * 128 + kg] : WR[u * 128 + kg - 128];
        kg++;
        f1 = (kg < 128) ? WL[u * 128 + kg] : WR[u * 128 + kg - 128];
        __half h0 = __float2half_rn(f0), h1 = __float2half_rn(f1);
        __half l0 = __float2half_rn(f0 - __half2float(h0));
        __half l1 = __float2half_rn(f1 - __half2float(h1));
        __half2 hp = __halves2half2(h0, h1), lp = __halves2half2(l0, l1);
        hu[j] = *(uint32_t*)&hp; lu[j] = *(uint32_t*)&lp;
    }
    *(uint4*)(hibase + off) = make_uint4(hu[0], hu[1], hu[2], hu[3]);
    *(uint4*)(lobase + off) = make_uint4(lu[0], lu[1], lu[2], lu[3]);
}

// ============================================================================
// mean1 (REDUCED): only r < Nn -> 5-row h1 means. Layer-1 tail (2-row h2
// means) and ALL layer-2 means are fused into producers.
// ============================================================================
__global__ void mean1_kernel(const float* __restrict__ h1)
{
    int idx = blockIdx.x * blockDim.x + threadIdx.x;
    if (idx >= Nn * 32) return;
    int r = idx >> 5, j = idx & 31;
    const float4* p = (const float4*)(h1 + (size_t)r * 640) + j;
    float4 a = p[0], b = p[32], c = p[64], d = p[96], e = p[128];
    float4 s;
    s.x = (a.x + b.x + c.x + d.x + e.x) * 0.2f;
    s.y = (a.y + b.y + c.y + d.y + e.y) * 0.2f;
    s.z = (a.z + b.z + c.z + d.z + e.z) * 0.2f;
    s.w = (a.w + b.w + c.w + d.w + e.w) * 0.2f;
    *((float4*)(g_means + (size_t)r * 128) + j) = s;
}

// ============================================================================
// PERSISTENT warp-specialized GEMM, fp16x3 split on mma.sync (HMMA).
// Pass 1 (Ah*Bh) -> f32 accum; passes 2,3 (Ah*Bl, Al*Bh) -> shared f16 accum.
// 384 threads: warps 0-7 MMA consumers (2M x 4N), warps 8-11 producers.
// Producer c>=2:
//   mode0, r<Nn  : read g_means (precomputed 5-row h1 means)
//   mode0, r>=Nn : FUSED 2-row h2 mean (4 loads/unit)
//   mode1        : FUSED 5-row g_outs-tail mean (10 loads/unit; only 782 jobs)
// B resident (128 KB). A double-buffered (2 x 32 KB). Named-barrier handoff.
// ============================================================================
#define SM_B    1024
#define SM_A    132096
#define SM_TOT  197632
#define NTHR    384
#define BAR_READY(s)    (1 + (s))
#define BAR_CONS(s)     (3 + (s))

extern "C" __global__ void __launch_bounds__(NTHR, 1)
signn_tile_kernel(int mode,
                  const float* __restrict__ h0,
                  const float* __restrict__ h1,
                  const float* __restrict__ h2,
                  float* __restrict__ outp)
{
    extern __shared__ __align__(1024) char smem[];
    const uint32_t sb = smem_u32(smem);
    const int tid = threadIdx.x, lane = tid & 31;
    const int y = blockIdx.x;
    const int nrows = mode ? Nn : ROWS1;
    const int ntiles = (nrows + 127) >> 7;
    const int stride = gridDim.y;

    // ---- stage B once (resident, 128 KB), all 384 threads ----
    {
        const uint4* bsrc = mode ? (const uint4*)&g_W2img[0][0][0]
                                 : (const uint4*)&g_W1img[y][0][0][0];
        uint4* bdst = (uint4*)(smem + SM_B);
        for (int i = tid; i < 8192; i += NTHR) bdst[i] = bsrc[i];
    }
    __syncthreads();

    if (tid < 256) {
        // ===================== CONSUMER: 8 MMA warps =====================
        const int wid = tid >> 5;
        const int wm = wid & 1;          // M warp group: 64 rows
        const int wn = wid >> 1;         // N warp group: 32 cols
        const int lrow = (lane & 7) + ((lane >> 3) & 1) * 8;
        const int lcol = lane >> 4;
        const int qlane = lane >> 2, tlane = lane & 3;

        int s = 0;
        for (int t = blockIdx.y; t < ntiles; t += stride) {
            const int row0 = t * 128;
            float acc[64];
            uint32_t accl[32];               // f16x2 accum for low passes
            #pragma unroll
            for (int i = 0; i < 64; i++) acc[i] = 0.0f;
            #pragma unroll
            for (int i = 0; i < 32; i++) accl[i] = 0u;

            #pragma unroll
            for (int c = 0; c < 4; c++) {
                barsync(BAR_READY(s), NTHR);          // wait A stage s filled
                const uint32_t aBase = sb + SM_A + s * 32768;
                const uint32_t bBase = sb + SM_B + c * 16384;
                #pragma unroll
                for (int kk = 0; kk < 4; kk++) {
                    uint32_t AH[4][4], AL[4][4], BH[2][4], BL[2][4];
                    #pragma unroll
                    for (int mf = 0; mf < 4; mf++) {
                        int r = wm * 64 + mf * 16 + lrow;
                        int u = kk * 2 + lcol;
                        ldm4(AH[mf], aBase + swz(r, u));
                        ldm4(AL[mf], aBase + 16384 + swz(r, u));
                    }
                    #pragma unroll
                    for (int nb = 0; nb < 2; nb++) {
                        int r = wn * 32 + nb * 16 + lrow;
                        int u = kk * 2 + lcol;
                        ldm4(BH[nb], bBase + swz(r, u));
                    }
                    // pass 1 (f32 acc) + pass 3 (f16 acc) use BH
                    #pragma unroll
                    for (int mf = 0; mf < 4; mf++)
                        #pragma unroll
                        for (int nb = 0; nb < 2; nb++)
                            #pragma unroll
                            for (int h = 0; h < 2; h++) {
                                mma16816(acc + mf * 16 + (nb * 2 + h) * 4,
                                         AH[mf], BH[nb][h], BH[nb][2 + h]);
                                mma16816h(accl + mf * 8 + (nb * 2 + h) * 2,
                                          AL[mf], BH[nb][h], BH[nb][2 + h]);
                            }
                    // pass 2 (f16 acc) uses BL
                    #pragma unroll
                    for (int nb = 0; nb < 2; nb++) {
                        int r = wn * 32 + nb * 16 + lrow;
                        int u = kk * 2 + lcol;
                        ldm4(BL[nb], bBase + 65536 + swz(r, u));
                    }
                    #pragma unroll
                    for (int mf = 0; mf < 4; mf++)
                        #pragma unroll
                        for (int nb = 0; nb < 2; nb++)
                            #pragma unroll
                            for (int h = 0; h < 2; h++)
                                mma16816h(accl + mf * 8 + (nb * 2 + h) * 2,
                                          AH[mf], BL[nb][h], BL[nb][2 + h]);
                }
                bararrive(BAR_CONS(s), NTHR);         // A stage s free
                s ^= 1;
            }

            // epilogue: merge f32 + f16 accums, apply sigmoid*spike
            #pragma unroll
            for (int mf = 0; mf < 4; mf++) {
                int r0 = row0 + wm * 64 + mf * 16 + qlane;
                #pragma unroll
                for (int nn = 0; nn < 4; nn++) {
                    const float* cc = acc + mf * 16 + nn * 4;
                    const uint32_t* cl = accl + mf * 8 + nn * 2;
                    int u = wn * 16 + nn * 4 + tlane;
                    #pragma unroll
                    for (int rr = 0; rr < 2; rr++) {
                        int r = r0 + rr * 8;
                        if (r < nrows) {
                            float2 lo = __half22float2(*(const __half2*)&cl[rr]);
                            float tt = cc[rr * 2 + 0] + lo.x;
                            float zz = cc[rr * 2 + 1] + lo.y;
                            float o = (tt >= 1.0f) ? (1.0f / (1.0f + __expf(-zz))) : 0.0f;
                            if (mode) outp[(size_t)r * 64 + u] = o;
                            else      g_outs[(size_t)r * 128 + y * 64 + u] = o;
                        }
                    }
                }
            }
        }
    } else {
        // ===================== PRODUCER: 4 warps (128 threads) ============
        const int ptid = tid - 256;
        const int k8 = ptid & 7;
        int s = 0;
        long jcount = 0;
        for (int t = blockIdx.y; t < ntiles; t += stride) {
            const int row0 = t * 128;
            #pragma unroll
            for (int c = 0; c < 4; c++) {
                // eager fetch (LDG issued before the stage wait)
                float4 pre[16];
                #pragma unroll
                for (int q = 0; q < 8; q++) {
                    int m = (ptid >> 3) + q * 16;
                    int r = row0 + m;
                    if (r < nrows) {
                        if (c < 2) {
                            const float* selfp = mode
                                ? g_outs + (size_t)r * 128
                                : ((r < Nn) ? h0 + (size_t)r * 128
                                            : h1 + (size_t)(r - Nn) * 128);
                            const float* p = selfp + c * 64 + k8 * 8;
                            pre[2 * q]     = *(const float4*)p;
                            pre[2 * q + 1] = *(const float4*)(p + 4);
                        } else if (mode == 0) {
                            if (r >= Nn) {
                                // fused 2-row h2 mean (identical arithmetic)
                                const float* p = h2 + (size_t)(r - Nn) * 256
                                                    + (c - 2) * 64 + k8 * 8;
                                float4 a0 = *(const float4*)p;
                                float4 a1 = *(const float4*)(p + 4);
                                float4 b0 = *(const float4*)(p + 128);
                                float4 b1 = *(const float4*)(p + 132);
                                float4 s0, s1;
                                s0.x = (a0.x + b0.x) * 0.5f; s0.y = (a0.y + b0.y) * 0.5f;
                                s0.z = (a0.z + b0.z) * 0.5f; s0.w = (a0.w + b0.w) * 0.5f;
                                s1.x = (a1.x + b1.x) * 0.5f; s1.y = (a1.y + b1.y) * 0.5f;
                                s1.z = (a1.z + b1.z) * 0.5f; s1.w = (a1.w + b1.w) * 0.5f;
                                pre[2 * q] = s0; pre[2 * q + 1] = s1;
                            } else {
                                const float* p = g_means + (size_t)r * 128
                                                         + (c - 2) * 64 + k8 * 8;
                                pre[2 * q]     = *(const float4*)p;
                                pre[2 * q + 1] = *(const float4*)(p + 4);
                            }
                        } else {
                            // fused 5-row g_outs-tail mean (== old mean2_kernel)
                            const float* p = g_outs
                                + ((size_t)Nn + (size_t)r * 5) * 128
                                + (c - 2) * 64 + k8 * 8;
                            float4 s0 = make_float4(0.f, 0.f, 0.f, 0.f), s1 = s0;
                            #pragma unroll
                            for (int i = 0; i < 5; i++) {
                                float4 a = *(const float4*)(p + i * 128);
                                float4 b = *(const float4*)(p + i * 128 + 4);
                                s0.x += a.x; s0.y += a.y; s0.z += a.z; s0.w += a.w;
                                s1.x += b.x; s1.y += b.y; s1.z += b.z; s1.w += b.w;
                            }
                            s0.x *= 0.2f; s0.y *= 0.2f; s0.z *= 0.2f; s0.w *= 0.2f;
                            s1.x *= 0.2f; s1.y *= 0.2f; s1.z *= 0.2f; s1.w *= 0.2f;
                            pre[2 * q] = s0; pre[2 * q + 1] = s1;
                        }
                    } else {
                        pre[2 * q] = pre[2 * q + 1] = make_float4(0.f, 0.f, 0.f, 0.f);
                    }
                }

                if (jcount >= 2) barsync(BAR_CONS(s), NTHR);

                char* Ah = smem + SM_A + s * 32768;
                char* Al = Ah + 16384;
                #pragma unroll
                for (int q = 0; q < 8; q++) {
                    int m = (ptid >> 3) + q * 16;
                    float f[8];
                    f[0]=pre[2*q].x; f[1]=pre[2*q].y; f[2]=pre[2*q].z; f[3]=pre[2*q].w;
                    f[4]=pre[2*q+1].x; f[5]=pre[2*q+1].y; f[6]=pre[2*q+1].z; f[7]=pre[2*q+1].w;
                    uint32_t hu[4], lu[4];
                    #pragma unroll
                    for (int j = 0; j < 4; j++) {
                        float x0 = f[2*j], x1 = f[2*j+1];
                        __half hh0 = __float2half_rn(x0), hh1 = __float2half_rn(x1);
                        __half ll0 = __float2half_rn(x0 - __half2float(hh0));
                        __half ll1 = __float2half_rn(x1 - __half2float(hh1));
                        __half2 hp = __halves2half2(hh0, hh1), lp = __halves2half2(ll0, ll1);
                        hu[j] = *(uint32_t*)&hp; lu[j] = *(uint32_t*)&lp;
                    }
                    int off = swz(m, k8);
                    *(uint4*)(Ah + off) = make_uint4(hu[0], hu[1], hu[2], hu[3]);
                    *(uint4*)(Al + off) = make_uint4(lu[0], lu[1], lu[2], lu[3]);
                }
                asm volatile("membar.cta;" ::: "memory");
                bararrive(BAR_READY(s), NTHR);
                s ^= 1;
                jcount++;
            }
        }
    }
}

// ============================================================================
extern "C" void kernel_launch(void* const* d_in, const int* in_sizes, int n_in,
                              void* d_out, int out_size)
{
    const float* h0   = (const float*)d_in[0];
    const float* h1   = (const float*)d_in[1];
    const float* h2   = (const float*)d_in[2];
    const float* Wl1  = (const float*)d_in[3];
    const float* Wr1  = (const float*)d_in[4];
    const float* Wlt1 = (const float*)d_in[5];
    const float* Wrt1 = (const float*)d_in[6];
    const float* Wl2  = (const float*)d_in[7];
    const float* Wr2  = (const float*)d_in[8];
    const float* Wlt2 = (const float*)d_in[9];
    const float* Wrt2 = (const float*)d_in[10];
    float* out = (float*)d_out;

    cudaFuncSetAttribute(signn_tile_kernel,
                         cudaFuncAttributeMaxDynamicSharedMemorySize, SM_TOT);

    prep_kernel<<<48, 256>>>(Wl1, Wr1, Wlt1, Wrt1, Wl2, Wr2, Wlt2, Wrt2);
    mean1_kernel<<<(Nn * 32 + 255) / 256, 256>>>(h1);    // 5-row h1 part only

    dim3 g1(2, 74);                    // 148 persistent CTAs
    signn_tile_kernel<<<g1, NTHR, SM_TOT>>>(0, h0, h1, h2, nullptr);

    dim3 g2(1, 148);                   // 148 persistent CTAs (mean2 fused)
    signn_tile_kernel<<<g2, NTHR, SM_TOT>>>(1, nullptr, nullptr, nullptr, out);
}